// round 16
// baseline (speedup 1.0000x reference)
#include <cuda_runtime.h>
#include <math.h>

// Problem shape (fixed by the dataset)
#define B  16
#define T  256
#define U  99
#define U1 100
#define V  128
#define KT 8                         // t-cells per chunk
#define NC (T / KT)                  // 32 chunks per row
#define RT 4                         // u-rows per lane
#define NTH 25                       // active DP lanes -> ONE warp
#define NSTEP (NC + NTH - 1)         // 56 wavefront steps (even)

#define LOG2E 1.4426950408889634f
#define LN2   0.6931471805599453f

// Scratch: LINEAR-domain probabilities, layout [b][u][t]
__device__ float g_blank[B * U1 * T];
__device__ float g_emit [B * U1 * T];
__device__ float g_cost [B];          // log2(alpha * blank) at (tl-1, ul)
__device__ int   g_done = 0;          // finish-fusion counter

__device__ __forceinline__ float ex2(float x) {
    float r; asm("ex2.approx.ftz.f32 %0, %1;" : "=f"(r) : "f"(x)); return r;
}
__device__ __forceinline__ float lg2(float x) {
    float r; asm("lg2.approx.ftz.f32 %0, %1;" : "=f"(r) : "f"(x)); return r;
}
__device__ __forceinline__ float rcp(float x) {
    float r; asm("rcp.approx.ftz.f32 %0, %1;" : "=f"(r) : "f"(x)); return r;
}

// ---------------------------------------------------------------------------
// Kernel 1: logsumexp + gather, length-skipped, linear-prob output (proven
// at 28.0us - useful-traffic floor for this length distribution).
// ---------------------------------------------------------------------------
__global__ __launch_bounds__(256) void rnnt_lse_kernel(
    const float* __restrict__ acts,
    const int*   __restrict__ labels,
    const int*   __restrict__ act_lens,
    const int*   __restrict__ label_lens)
{
    const int warp = threadIdx.x >> 5;
    const int lane = threadIdx.x & 31;

    const int t = blockIdx.x & (T - 1);
    const int b = blockIdx.x >> 8;          // T = 256

    const int tl = act_lens[b];
    if (t >= tl) return;
    const int ul = label_lens[b];

    const float* base = acts + ((size_t)(b * T + t)) * U1 * V;

    #pragma unroll 1
    for (int ubase = 0; ubase <= ul; ubase += 16) {
        const int u0 = ubase + warp;
        const int u1 = u0 + 8;
        const bool has0 = (u0 <= ul);
        const bool has1 = (u1 <= ul);

        float4 v0 = make_float4(0.f, 0.f, 0.f, 0.f);
        float4 v1 = make_float4(0.f, 0.f, 0.f, 0.f);
        if (has0) v0 = __ldcs(reinterpret_cast<const float4*>(base + u0 * V) + lane);
        if (has1) v1 = __ldcs(reinterpret_cast<const float4*>(base + u1 * V) + lane);

        float s0 = ex2(v0.x * LOG2E) + ex2(v0.y * LOG2E)
                 + ex2(v0.z * LOG2E) + ex2(v0.w * LOG2E);
        float s1 = ex2(v1.x * LOG2E) + ex2(v1.y * LOG2E)
                 + ex2(v1.z * LOG2E) + ex2(v1.w * LOG2E);
        #pragma unroll
        for (int o = 16; o; o >>= 1) {
            s0 += __shfl_xor_sync(0xFFFFFFFFu, s0, o);
            s1 += __shfl_xor_sync(0xFFFFFFFFu, s1, o);
        }
        const float lse0 = lg2(s0);
        const float lse1 = lg2(s1);

        const float blank0 = __shfl_sync(0xFFFFFFFFu, v0.x, 0);
        const float blank1 = __shfl_sync(0xFFFFFFFFu, v1.x, 0);

        float ev0, ev1;
        {
            const int l0 = (has0 && u0 < U) ? labels[b * U + u0] : 0;
            const float c0 = ((l0 & 3) == 0) ? v0.x : ((l0 & 3) == 1) ? v0.y
                           : ((l0 & 3) == 2) ? v0.z : v0.w;
            ev0 = __shfl_sync(0xFFFFFFFFu, c0, l0 >> 2);
            const int l1 = (has1 && u1 < U) ? labels[b * U + u1] : 0;
            const float c1 = ((l1 & 3) == 0) ? v1.x : ((l1 & 3) == 1) ? v1.y
                           : ((l1 & 3) == 2) ? v1.z : v1.w;
            ev1 = __shfl_sync(0xFFFFFFFFu, c1, l1 >> 2);
        }

        if (lane == 0) {
            if (has0) {
                const int o0 = (b * U1 + u0) * T + t;
                g_blank[o0] = ex2(blank0 * LOG2E - lse0);
                if (u0 < U) g_emit[o0] = ex2(ev0 * LOG2E - lse0);
            }
            if (has1) {
                const int o1 = (b * U1 + u1) * T + t;
                g_blank[o1] = ex2(blank1 * LOG2E - lse1);
                if (u1 < U) g_emit[o1] = ex2(ev1 * LOG2E - lse1);
            }
        }
    }
}

// ---------------------------------------------------------------------------
// DP step: prefetch chunk c+1 into (BlW, EmW) FIRST (full-step latency
// cover), then shuffles, then compute chunk c from (BlR, EmR).
// ---------------------------------------------------------------------------
__device__ __forceinline__ void dp_step(
    const int m, const int i, const bool valid,
    const int tl, const int ul, const int b,
    float (&BlR)[RT][KT], float (&EmR)[RT][KT],
    float (&BlW)[RT][KT], float (&EmW)[RT][KT],
    float (&my_a)[RT], float (&Blast)[RT],
    float &pa0, float (&pW)[KT],
    const float* __restrict__ gB, const float* __restrict__ gE)
{
    const int c  = m - i;
    const int t0 = c * KT;

    // 1) prefetch chunk c+1 (consumed next step)
    {
        const int c1 = c + 1;
        if (valid && c1 >= 0 && c1 < NC) {
            const int t0n = c1 * KT;
            #pragma unroll
            for (int r = 0; r < RT; ++r) {
                const float* pb = gB + (RT * i + r) * T + t0n;
                const float* pe = gE + (RT * i + r) * T + t0n;
                const float4 b0 = __ldg((const float4*)pb);
                const float4 b1 = __ldg((const float4*)(pb + 4));
                const float4 e0 = __ldg((const float4*)pe);
                const float4 e1 = __ldg((const float4*)(pe + 4));
                BlW[r][0]=b0.x; BlW[r][1]=b0.y; BlW[r][2]=b0.z; BlW[r][3]=b0.w;
                BlW[r][4]=b1.x; BlW[r][5]=b1.y; BlW[r][6]=b1.z; BlW[r][7]=b1.w;
                EmW[r][0]=e0.x; EmW[r][1]=e0.y; EmW[r][2]=e0.z; EmW[r][3]=e0.w;
                EmW[r][4]=e1.x; EmW[r][5]=e1.y; EmW[r][6]=e1.z; EmW[r][7]=e1.w;
            }
        }
    }

    // 2) previous-step publishes from lane i-1
    const float sa0 = __shfl_up_sync(0xFFFFFFFFu, pa0, 1);
    float sW[KT];
    #pragma unroll
    for (int k = 0; k < KT; ++k) sW[k] = __shfl_up_sync(0xFFFFFFFFu, pW[k], 1);

    // 3) compute chunk c
    if (valid && c >= 0 && c < NC) {
        float a0s, Ws[KT];
        if (i == 0) {
            a0s = my_a[0];
            #pragma unroll
            for (int k = 0; k < KT; ++k) Ws[k] = 0.f;
        } else {
            a0s = sa0;
            #pragma unroll
            for (int k = 0; k < KT; ++k) Ws[k] = sW[k];
        }

        #pragma unroll
        for (int r = 0; r < RT; ++r) {
            const int u = RT * i + r;
            const float up = (t0 > 0) ? ex2(my_a[r] - a0s) * Blast[r] : 0.f;
            const float S  = up + Ws[0];
            float a0    = a0s + lg2(S);
            float scale = rcp(S);
            if (t0 == 0 && u == 0) { a0 = 0.f; scale = 0.f; }

            float P[KT];
            P[0] = 1.f;
            {
                float p = BlR[r][0] + Ws[1] * scale;
                P[1] = p;
                #pragma unroll
                for (int k = 2; k < KT; ++k) {
                    p = p * BlR[r][k - 1] + Ws[k] * scale;
                    P[k] = p;
                }
            }
            my_a[r]  = a0 + lg2(P[KT - 1]);
            Blast[r] = BlR[r][KT - 1];

            if (u == ul) {
                const int kk = tl - 1 - t0;
                if (kk >= 0 && kk < KT) {
                    float Pk = P[0], Bk = BlR[r][0];
                    #pragma unroll
                    for (int k = 1; k < KT; ++k)
                        if (k == kk) { Pk = P[k]; Bk = BlR[r][k]; }
                    g_cost[b] = a0 + lg2(Pk * Bk);
                }
            }

            a0s = a0;
            #pragma unroll
            for (int k = 0; k < KT; ++k) Ws[k] = P[k] * EmR[r][k];
        }
        pa0 = a0s;
        #pragma unroll
        for (int k = 0; k < KT; ++k) pW[k] = Ws[k];
    }
}

// ---------------------------------------------------------------------------
// Kernel 2: SINGLE-WARP wavefront DP, R=4 rows/lane, KT=8, 56 steps.
// Double-buffered register prefetch (A/B, unroll-2 parity): loads for the
// next chunk issue at the TOP of each step -> full-step latency cover.
// ---------------------------------------------------------------------------
__global__ __launch_bounds__(32) void rnnt_dp_kernel(
    const int* __restrict__ act_lens,
    const int* __restrict__ label_lens,
    float* __restrict__ out)
{
    const int b = blockIdx.x;
    const int i = threadIdx.x;
    const bool valid = (i < NTH);

    const int tl = act_lens[b];
    const int ul = label_lens[b];

    const float* __restrict__ gB = g_blank + (size_t)b * U1 * T;
    const float* __restrict__ gE = g_emit  + (size_t)b * U1 * T;

    float my_a[RT], Blast[RT];
    float BlA[RT][KT], EmA[RT][KT], BlB[RT][KT], EmB[RT][KT];
    float pa0 = 0.f, pW[KT];
    #pragma unroll
    for (int r = 0; r < RT; ++r) { my_a[r] = -INFINITY; Blast[r] = 1.f; }
    #pragma unroll
    for (int k = 0; k < KT; ++k) pW[k] = 0.f;

    // preload chunk 0 into buffer A (only lane 0 is active at m=0)
    if (i == 0) {
        #pragma unroll
        for (int r = 0; r < RT; ++r) {
            const float4 b0 = __ldg((const float4*)(gB + r * T));
            const float4 b1 = __ldg((const float4*)(gB + r * T + 4));
            const float4 e0 = __ldg((const float4*)(gE + r * T));
            const float4 e1 = __ldg((const float4*)(gE + r * T + 4));
            BlA[r][0]=b0.x; BlA[r][1]=b0.y; BlA[r][2]=b0.z; BlA[r][3]=b0.w;
            BlA[r][4]=b1.x; BlA[r][5]=b1.y; BlA[r][6]=b1.z; BlA[r][7]=b1.w;
            EmA[r][0]=e0.x; EmA[r][1]=e0.y; EmA[r][2]=e0.z; EmA[r][3]=e0.w;
            EmA[r][4]=e1.x; EmA[r][5]=e1.y; EmA[r][6]=e1.z; EmA[r][7]=e1.w;
        }
    }

    #pragma unroll 1
    for (int m = 0; m < NSTEP; m += 2) {
        dp_step(m,     i, valid, tl, ul, b, BlA, EmA, BlB, EmB,
                my_a, Blast, pa0, pW, gB, gE);
        dp_step(m + 1, i, valid, tl, ul, b, BlB, EmB, BlA, EmA,
                my_a, Blast, pa0, pW, gB, gE);
    }

    // ---- fused finish: last block of the 16 reduces and writes out ----
    __syncwarp();
    if (i == 0) {
        __threadfence();
        const int done = atomicAdd(&g_done, 1);
        if (done == B - 1) {
            g_done = 0;
            float s = 0.f;
            #pragma unroll
            for (int k = 0; k < B; ++k) s += g_cost[k];
            out[0] = -s * LN2 * (1.0f / B);
        }
    }
}

// ---------------------------------------------------------------------------
extern "C" void kernel_launch(void* const* d_in, const int* in_sizes, int n_in,
                              void* d_out, int out_size)
{
    const float* acts       = (const float*)d_in[0];
    const int*   labels     = (const int*)  d_in[1];
    const int*   act_lens   = (const int*)  d_in[2];
    const int*   label_lens = (const int*)  d_in[3];

    rnnt_lse_kernel<<<B * T, 256>>>(acts, labels, act_lens, label_lens);
    rnnt_dp_kernel<<<B, 32>>>(act_lens, label_lens, (float*)d_out);
}

// round 17
// speedup vs baseline: 1.2844x; 1.2844x over previous
#include <cuda_runtime.h>
#include <math.h>
#include <stdint.h>

// Problem shape (fixed by the dataset)
#define B  16
#define T  256
#define U  99
#define U1 100
#define V  128
#define KT 8                         // t-cells per chunk
#define NC (T / KT)                  // 32 chunks per row
#define RT 4                         // u-rows per lane
#define NTH 25                       // active DP lanes -> ONE warp
#define NSTEP (NC + NTH - 1)         // 56 wavefront steps

#define LOG2E 1.4426950408889634f
#define LN2   0.6931471805599453f

#define LSTRIDE 68                   // floats per lane per buffer (64 + pad 4)

// Scratch: LINEAR-domain probabilities, layout [b][u][t]
__device__ float g_blank[B * U1 * T];
__device__ float g_emit [B * U1 * T];
__device__ float g_cost [B];          // log2(alpha * blank) at (tl-1, ul)
__device__ int   g_done = 0;          // finish-fusion counter

__device__ __forceinline__ float ex2(float x) {
    float r; asm("ex2.approx.ftz.f32 %0, %1;" : "=f"(r) : "f"(x)); return r;
}
__device__ __forceinline__ float lg2(float x) {
    float r; asm("lg2.approx.ftz.f32 %0, %1;" : "=f"(r) : "f"(x)); return r;
}
__device__ __forceinline__ float rcp(float x) {
    float r; asm("rcp.approx.ftz.f32 %0, %1;" : "=f"(r) : "f"(x)); return r;
}
__device__ __forceinline__ void cp16(uint32_t saddr, const void* gaddr) {
    asm volatile("cp.async.ca.shared.global [%0], [%1], 16;"
                 :: "r"(saddr), "l"(gaddr));
}
__device__ __forceinline__ void cp_commit() {
    asm volatile("cp.async.commit_group;");
}
__device__ __forceinline__ void cp_wait1() {
    asm volatile("cp.async.wait_group 1;");
}
__device__ __forceinline__ void cp_wait0() {
    asm volatile("cp.async.wait_group 0;");
}

// ---------------------------------------------------------------------------
// Kernel 1: logsumexp + gather, length-skipped, linear-prob output (proven
// at 28.0us — useful-traffic floor for this length distribution).
// ---------------------------------------------------------------------------
__global__ __launch_bounds__(256) void rnnt_lse_kernel(
    const float* __restrict__ acts,
    const int*   __restrict__ labels,
    const int*   __restrict__ act_lens,
    const int*   __restrict__ label_lens)
{
    const int warp = threadIdx.x >> 5;
    const int lane = threadIdx.x & 31;

    const int t = blockIdx.x & (T - 1);
    const int b = blockIdx.x >> 8;          // T = 256

    const int tl = act_lens[b];
    if (t >= tl) return;
    const int ul = label_lens[b];

    const float* base = acts + ((size_t)(b * T + t)) * U1 * V;

    #pragma unroll 1
    for (int ubase = 0; ubase <= ul; ubase += 16) {
        const int u0 = ubase + warp;
        const int u1 = u0 + 8;
        const bool has0 = (u0 <= ul);
        const bool has1 = (u1 <= ul);

        float4 v0 = make_float4(0.f, 0.f, 0.f, 0.f);
        float4 v1 = make_float4(0.f, 0.f, 0.f, 0.f);
        if (has0) v0 = __ldcs(reinterpret_cast<const float4*>(base + u0 * V) + lane);
        if (has1) v1 = __ldcs(reinterpret_cast<const float4*>(base + u1 * V) + lane);

        float s0 = ex2(v0.x * LOG2E) + ex2(v0.y * LOG2E)
                 + ex2(v0.z * LOG2E) + ex2(v0.w * LOG2E);
        float s1 = ex2(v1.x * LOG2E) + ex2(v1.y * LOG2E)
                 + ex2(v1.z * LOG2E) + ex2(v1.w * LOG2E);
        #pragma unroll
        for (int o = 16; o; o >>= 1) {
            s0 += __shfl_xor_sync(0xFFFFFFFFu, s0, o);
            s1 += __shfl_xor_sync(0xFFFFFFFFu, s1, o);
        }
        const float lse0 = lg2(s0);
        const float lse1 = lg2(s1);

        const float blank0 = __shfl_sync(0xFFFFFFFFu, v0.x, 0);
        const float blank1 = __shfl_sync(0xFFFFFFFFu, v1.x, 0);

        float ev0, ev1;
        {
            const int l0 = (has0 && u0 < U) ? labels[b * U + u0] : 0;
            const float c0 = ((l0 & 3) == 0) ? v0.x : ((l0 & 3) == 1) ? v0.y
                           : ((l0 & 3) == 2) ? v0.z : v0.w;
            ev0 = __shfl_sync(0xFFFFFFFFu, c0, l0 >> 2);
            const int l1 = (has1 && u1 < U) ? labels[b * U + u1] : 0;
            const float c1 = ((l1 & 3) == 0) ? v1.x : ((l1 & 3) == 1) ? v1.y
                           : ((l1 & 3) == 2) ? v1.z : v1.w;
            ev1 = __shfl_sync(0xFFFFFFFFu, c1, l1 >> 2);
        }

        if (lane == 0) {
            if (has0) {
                const int o0 = (b * U1 + u0) * T + t;
                g_blank[o0] = ex2(blank0 * LOG2E - lse0);
                if (u0 < U) g_emit[o0] = ex2(ev0 * LOG2E - lse0);
            }
            if (has1) {
                const int o1 = (b * U1 + u1) * T + t;
                g_blank[o1] = ex2(blank1 * LOG2E - lse1);
                if (u1 < U) g_emit[o1] = ex2(ev1 * LOG2E - lse1);
            }
        }
    }
}

// ---------------------------------------------------------------------------
// Kernel 2: SINGLE-WARP wavefront DP, R=4 rows/lane, KT=8, 56 steps.
// Prefetch via cp.async into a double-buffered smem stage (ZERO destination
// registers -> ptxas can keep the compute chain tight; fixes round-16's
// register-pressure-killed prefetch). Per-thread commit/wait groups, no
// barriers: each lane reads only the data it staged itself.
// smem layout per buffer: lane*68 floats = [Bl[4][8] | Em[4][8] | pad 4]
// (68*4 = 272B per lane -> 4-way worst-case bank conflict on LDS.128).
// ---------------------------------------------------------------------------
__global__ __launch_bounds__(32) void rnnt_dp_kernel(
    const int* __restrict__ act_lens,
    const int* __restrict__ label_lens,
    float* __restrict__ out)
{
    __shared__ float sbuf[2][32 * LSTRIDE];

    const int b = blockIdx.x;
    const int i = threadIdx.x;
    const bool valid = (i < NTH);

    const int tl = act_lens[b];
    const int ul = label_lens[b];

    const float* __restrict__ gB = g_blank + (size_t)b * U1 * T;
    const float* __restrict__ gE = g_emit  + (size_t)b * U1 * T;

    float my_a[RT], Blast[RT];
    float pa0 = 0.f, pW[KT];
    #pragma unroll
    for (int r = 0; r < RT; ++r) { my_a[r] = -INFINITY; Blast[r] = 1.f; }
    #pragma unroll
    for (int k = 0; k < KT; ++k) pW[k] = 0.f;

    const uint32_t s0addr = (uint32_t)__cvta_generic_to_shared(&sbuf[0][i * LSTRIDE]);
    const uint32_t s1addr = (uint32_t)__cvta_generic_to_shared(&sbuf[1][i * LSTRIDE]);

    // helper lambda: issue the 16 cp.asyncs for chunk c into buffer buf
    auto issue_chunk = [&](int c, int buf) {
        if (valid && c >= 0 && c < NC) {
            const int t0 = c * KT;
            const uint32_t sa = buf ? s1addr : s0addr;
            #pragma unroll
            for (int r = 0; r < RT; ++r) {
                const float* pb = gB + (RT * i + r) * T + t0;
                const float* pe = gE + (RT * i + r) * T + t0;
                cp16(sa + (r * 8) * 4,        pb);
                cp16(sa + (r * 8 + 4) * 4,    pb + 4);
                cp16(sa + (32 + r * 8) * 4,   pe);
                cp16(sa + (32 + r * 8 + 4) * 4, pe + 4);
            }
        }
        cp_commit();   // every lane commits every step (uniform group count)
    };

    // preload chunk 0 (only lane 0 has a valid chunk at m=0) into buf 0
    issue_chunk(0 - i, 0);

    #pragma unroll 1
    for (int m = 0; m < NSTEP; ++m) {
        const int c  = m - i;
        const int t0 = c * KT;

        // prefetch chunk c+1 into the other buffer, then ensure the
        // current chunk's group (committed last step) has landed.
        issue_chunk(c + 1, (m + 1) & 1);
        cp_wait1();

        // previous-step publishes from lane i-1
        const float sa0 = __shfl_up_sync(0xFFFFFFFFu, pa0, 1);
        float sW[KT];
        #pragma unroll
        for (int k = 0; k < KT; ++k) sW[k] = __shfl_up_sync(0xFFFFFFFFu, pW[k], 1);

        if (valid && c >= 0 && c < NC) {
            const float* lbase = &sbuf[m & 1][i * LSTRIDE];

            float a0s, Ws[KT];
            if (i == 0) {
                a0s = my_a[0];
                #pragma unroll
                for (int k = 0; k < KT; ++k) Ws[k] = 0.f;
            } else {
                a0s = sa0;
                #pragma unroll
                for (int k = 0; k < KT; ++k) Ws[k] = sW[k];
            }

            #pragma unroll
            for (int r = 0; r < RT; ++r) {
                const int u = RT * i + r;

                const float4 bl0 = *reinterpret_cast<const float4*>(lbase + r * 8);
                const float4 bl1 = *reinterpret_cast<const float4*>(lbase + r * 8 + 4);
                const float4 em0 = *reinterpret_cast<const float4*>(lbase + 32 + r * 8);
                const float4 em1 = *reinterpret_cast<const float4*>(lbase + 32 + r * 8 + 4);
                const float Bl[KT] = {bl0.x, bl0.y, bl0.z, bl0.w,
                                      bl1.x, bl1.y, bl1.z, bl1.w};
                const float Em[KT] = {em0.x, em0.y, em0.z, em0.w,
                                      em1.x, em1.y, em1.z, em1.w};

                const float up = (t0 > 0) ? ex2(my_a[r] - a0s) * Blast[r] : 0.f;
                const float S  = up + Ws[0];
                float a0    = a0s + lg2(S);
                float scale = rcp(S);
                if (t0 == 0 && u == 0) { a0 = 0.f; scale = 0.f; }

                float P[KT];
                P[0] = 1.f;
                {
                    float p = Bl[0] + Ws[1] * scale;
                    P[1] = p;
                    #pragma unroll
                    for (int k = 2; k < KT; ++k) {
                        p = p * Bl[k - 1] + Ws[k] * scale;
                        P[k] = p;
                    }
                }
                my_a[r]  = a0 + lg2(P[KT - 1]);
                Blast[r] = Bl[KT - 1];

                if (u == ul) {
                    const int kk = tl - 1 - t0;
                    if (kk >= 0 && kk < KT) {
                        float Pk = P[0], Bk = Bl[0];
                        #pragma unroll
                        for (int k = 1; k < KT; ++k)
                            if (k == kk) { Pk = P[k]; Bk = Bl[k]; }
                        g_cost[b] = a0 + lg2(Pk * Bk);
                    }
                }

                a0s = a0;
                #pragma unroll
                for (int k = 0; k < KT; ++k) Ws[k] = P[k] * Em[k];
            }
            pa0 = a0s;
            #pragma unroll
            for (int k = 0; k < KT; ++k) pW[k] = Ws[k];
        }
    }
    cp_wait0();

    // ---- fused finish: last block of the 16 reduces and writes out ----
    __syncwarp();
    if (i == 0) {
        __threadfence();
        const int done = atomicAdd(&g_done, 1);
        if (done == B - 1) {
            g_done = 0;
            float s = 0.f;
            #pragma unroll
            for (int k = 0; k < B; ++k) s += g_cost[k];
            out[0] = -s * LN2 * (1.0f / B);
        }
    }
}

// ---------------------------------------------------------------------------
extern "C" void kernel_launch(void* const* d_in, const int* in_sizes, int n_in,
                              void* d_out, int out_size)
{
    const float* acts       = (const float*)d_in[0];
    const int*   labels     = (const int*)  d_in[1];
    const int*   act_lens   = (const int*)  d_in[2];
    const int*   label_lens = (const int*)  d_in[3];

    rnnt_lse_kernel<<<B * T, 256>>>(acts, labels, act_lens, label_lens);
    rnnt_dp_kernel<<<B, 32>>>(act_lens, label_lens, (float*)d_out);
}